// round 7
// baseline (speedup 1.0000x reference)
#include <cuda_runtime.h>
#include <cuda.h>
#include <cuda_fp16.h>
#include <cstdint>

// Problem constants
#define BSZ   16384
#define SE    2048
#define SO    2048
#define H1    1024
#define NSTEP 10

// GEMM tiling: CTA tile 128 x 256, warp tile 64 x 64 (8 warps: 2M x 4N)
#define BM 128
#define BN 256
#define BK 64
#define STG 3
#define ATILE 16384                       // 128 rows x 128 B
#define BTILE 32768                       // 256 rows x 128 B
#define STAGE_BYTES (ATILE + BTILE)       // 49152
#define SMEM_ALLOC (STG * STAGE_BYTES + 1024)   // 148480 -> 1 CTA/SM

// ---------------------------------------------------------------------------
// Scratch (device globals; no allocation allowed)
// ---------------------------------------------------------------------------
__device__ __align__(1024) __half g_A1[(size_t)BSZ * SE];   // rho(s_even)-0.5
__device__ __align__(1024) __half g_A2[(size_t)BSZ * SE];   // rho(s_odd)-0.5
__device__ __align__(1024) __half g_W1[(size_t)SO * SE];    // W1[n][k] = W[k][n]
__device__ __align__(1024) __half g_W2[(size_t)SE * SO];    // W2[n][k] = W[n][k]
__device__ float g_csum1[SO];
__device__ float g_csum2[SE];

// ---------------------------------------------------------------------------
// Helpers
// ---------------------------------------------------------------------------
__device__ __forceinline__ float ex2f(float x) {
    float y; asm("ex2.approx.f32 %0, %1;" : "=f"(y) : "f"(x)); return y;
}
__device__ __forceinline__ float rcpf(float x) {
    float y; asm("rcp.approx.f32 %0, %1;" : "=f"(y) : "f"(x)); return y;
}
__device__ __forceinline__ float tanh_ap(float x) {
    float y; asm("tanh.approx.f32 %0, %1;" : "=f"(y) : "f"(x)); return y;
}
#define RHO_A (-5.770780163555852f)
#define RHO_B ( 2.885390081777926f)
__device__ __forceinline__ float rho_f(float x) {
    float q = ex2f(fmaf(RHO_A, x, RHO_B));
    return rcpf(1.0f + q);
}
__device__ __forceinline__ uint32_t cvta_smem(const void* p) {
    uint32_t a;
    asm("{ .reg .u64 t; cvta.to.shared.u64 t, %1; cvt.u32.u64 %0, t; }" : "=r"(a) : "l"(p));
    return a;
}
__device__ __forceinline__ void mbar_init(uint32_t a, uint32_t cnt) {
    asm volatile("mbarrier.init.shared.b64 [%0], %1;" :: "r"(a), "r"(cnt) : "memory");
}
__device__ __forceinline__ void mbar_expect_tx(uint32_t a, uint32_t b) {
    asm volatile("mbarrier.arrive.expect_tx.shared.b64 _, [%0], %1;" :: "r"(a), "r"(b) : "memory");
}
__device__ __forceinline__ void mbar_wait(uint32_t a, uint32_t ph) {
    asm volatile(
        "{\n\t.reg .pred P;\n"
        "LW%=:\n\t"
        "mbarrier.try_wait.parity.acquire.cta.shared::cta.b64 P, [%0], %1, 0x989680;\n\t"
        "@P bra LD%=;\n\t"
        "bra LW%=;\n"
        "LD%=:\n\t}"
        :: "r"(a), "r"(ph) : "memory");
}
__device__ __forceinline__ void tma2d(uint32_t dst, const CUtensorMap* tm, int x, int y, uint32_t mbar) {
    asm volatile(
        "cp.async.bulk.tensor.2d.shared::cta.global.tile.mbarrier::complete_tx::bytes "
        "[%0], [%1, {%2, %3}], [%4];"
        :: "r"(dst), "l"(tm), "r"(x), "r"(y), "r"(mbar) : "memory");
}
__device__ __forceinline__ void mma16816(float d[4], const uint32_t a[4], uint32_t b0, uint32_t b1) {
    asm volatile(
        "mma.sync.aligned.m16n8k16.row.col.f32.f16.f16.f32 "
        "{%0,%1,%2,%3}, {%4,%5,%6,%7}, {%8,%9}, {%0,%1,%2,%3};\n"
        : "+f"(d[0]), "+f"(d[1]), "+f"(d[2]), "+f"(d[3])
        : "r"(a[0]), "r"(a[1]), "r"(a[2]), "r"(a[3]), "r"(b0), "r"(b1));
}
__device__ __forceinline__ void ldsm4(uint32_t f[4], uint32_t addr) {
    asm volatile("ldmatrix.sync.aligned.m8n8.x4.shared.b16 {%0,%1,%2,%3}, [%4];\n"
                 : "=r"(f[0]), "=r"(f[1]), "=r"(f[2]), "=r"(f[3]) : "r"(addr));
}

// ---------------------------------------------------------------------------
// Prep kernels
// ---------------------------------------------------------------------------
__global__ void prepA_kernel(const float* __restrict__ s) {
    int id = blockIdx.x * blockDim.x + threadIdx.x;
    int m  = id >> 9;
    int kc = id & 511;
    float4 x = reinterpret_cast<const float4*>(s + (size_t)m * (SE + SO))[kc];
    float r0 = rho_f(x.x) - 0.5f;
    float r1 = rho_f(x.y) - 0.5f;
    float r2 = rho_f(x.z) - 0.5f;
    float r3 = rho_f(x.w) - 0.5f;
    __half2* dst = reinterpret_cast<__half2*>(g_A1 + (size_t)m * SE);
    dst[kc * 2 + 0] = __floats2half2_rn(r0, r1);
    dst[kc * 2 + 1] = __floats2half2_rn(r2, r3);
}

__global__ void prepW_kernel(const float* __restrict__ W) {
    __shared__ float tile[32][33];
    int bx = blockIdx.x * 32;   // n
    int by = blockIdx.y * 32;   // k
    int tx = threadIdx.x, ty = threadIdx.y;   // 32 x 8
#pragma unroll
    for (int j = 0; j < 32; j += 8) {
        int r = by + ty + j, c = bx + tx;
        float w = W[(size_t)r * SO + c];
        g_W2[(size_t)r * SO + c] = __float2half(w);
        tile[ty + j][tx] = w;
    }
    __syncthreads();
#pragma unroll
    for (int j = 0; j < 32; j += 8) {
        float w = tile[tx][ty + j];
        g_W1[(size_t)(bx + ty + j) * SE + by + tx] = __float2half(w);
    }
}

__global__ void prepSums_kernel(const float* __restrict__ W,
                                const float* __restrict__ b_even,
                                const float* __restrict__ b_odd) {
    if (blockIdx.x < 2048) {
        __shared__ float red[256];
        int n = blockIdx.x;
        float p = 0.f;
        for (int k = threadIdx.x; k < SO; k += 256) p += W[(size_t)n * SO + k];
        red[threadIdx.x] = p;
        __syncthreads();
        for (int st = 128; st > 0; st >>= 1) {
            if (threadIdx.x < st) red[threadIdx.x] += red[threadIdx.x + st];
            __syncthreads();
        }
        if (threadIdx.x == 0) g_csum2[n] = 0.5f * red[0] + b_even[n];
    } else {
        int c = (blockIdx.x - 2048) * 256 + threadIdx.x;
        float sum = 0.f;
        for (int k = 0; k < SE; k++) sum += W[(size_t)k * SO + c];
        g_csum1[c] = 0.5f * sum + b_odd[c];
    }
}

// ---------------------------------------------------------------------------
// Fused GEMM (TMA + HMMA, 64x64 warp tiles) + fixed-point iteration
// ---------------------------------------------------------------------------
template <int PHASE>
__global__ void __launch_bounds__(256, 1)
gemm_fused(const __grid_constant__ CUtensorMap tmA,
           const __grid_constant__ CUtensorMap tmB,
           const float* __restrict__ s_in, const float* __restrict__ Ux,
           float* __restrict__ out) {
    extern __shared__ char smem[];
    const uint32_t s0 = cvta_smem(smem);
    const float* csum_g = (PHASE == 1) ? g_csum1 : g_csum2;

    const int tid  = threadIdx.x;
    const int warp = tid >> 5, lane = tid & 31;
    const int wm = warp & 1, wn = warp >> 1;     // 2 warps along M, 4 along N (64 cols each)
    const int m0 = blockIdx.y * BM;
    const int n0 = blockIdx.x * BN;

    // block-sparse K range
    int k_lo, k_hi;
    if (PHASE == 1) { k_lo = 0; k_hi = (n0 < H1) ? 1024 : 2048; }
    else            { k_lo = (n0 < H1) ? 0 : 1024; k_hi = 2048; }
    const int total = (k_hi - k_lo) >> 6;        // 16 or 32 k-tiles, >= STG

    const uint32_t fullb = s0;                   // STG x 8 B barriers
    const uint32_t tbase = s0 + 1024;

    if (tid == 0) {
#pragma unroll
        for (int i = 0; i < STG; i++) mbar_init(fullb + 8 * i, 1);
    }
    __syncthreads();

    auto issue_stage = [&](int st) {
        const int b = st % STG;
        const uint32_t mb = fullb + 8 * b;
        const int kt = k_lo + st * BK;
        const uint32_t d = tbase + b * STAGE_BYTES;
        mbar_expect_tx(mb, STAGE_BYTES);
        tma2d(d,         &tmA, kt, m0, mb);      // 64x128 box (A)
        tma2d(d + ATILE, &tmB, kt, n0, mb);      // 64x256 box (B)
    };

    if (tid == 0) {
#pragma unroll
        for (int st = 0; st < STG; st++) issue_stage(st);
    }

    // loop-invariant ldmatrix address components
    const uint32_t arow = wm * 64 + (lane & 15);
    const uint32_t abit = (lane >> 4);
    const uint32_t brow = wn * 64 + ((lane >> 4) << 3) + (lane & 7);
    const uint32_t bbit = ((lane >> 3) & 1);

    float acc[4][8][4];
#pragma unroll
    for (int a = 0; a < 4; a++)
#pragma unroll
        for (int b = 0; b < 8; b++)
#pragma unroll
            for (int c = 0; c < 4; c++) acc[a][b][c] = 0.f;

    for (int st = 0; st < total; st++) {
        const int buf = st % STG;
        mbar_wait(fullb + 8 * buf, (st / STG) & 1);

        const uint32_t bufA = tbase + buf * STAGE_BYTES;
        const uint32_t bufB = bufA + ATILE;

        uint32_t af[2][4][4];
        uint32_t bf[2][4][4];

        auto ldfrags = [&](int ks, int slot) {
#pragma unroll
            for (int mi = 0; mi < 4; mi++) {
                uint32_t row = arow + mi * 16;
                uint32_t chunk = (ks * 2 + abit) ^ (row & 7);
                ldsm4(af[slot][mi], bufA + row * 128 + (chunk << 4));
            }
#pragma unroll
            for (int nj = 0; nj < 4; nj++) {
                uint32_t row = brow + nj * 16;
                uint32_t chunk = (ks * 2 + bbit) ^ (row & 7);
                ldsm4(bf[slot][nj], bufB + row * 128 + (chunk << 4));
            }
        };

        ldfrags(0, 0);
#pragma unroll
        for (int ks = 0; ks < 4; ks++) {
            const int cur = ks & 1;
            if (ks < 3) ldfrags(ks + 1, cur ^ 1);
#pragma unroll
            for (int mi = 0; mi < 4; mi++)
#pragma unroll
                for (int ni = 0; ni < 8; ni++)
                    mma16816(acc[mi][ni], af[cur][mi],
                             bf[cur][ni >> 1][(ni & 1) * 2],
                             bf[cur][ni >> 1][(ni & 1) * 2 + 1]);
        }
        __syncthreads();                      // all warps done with this buffer
        if (st + STG < total && tid == 0) issue_stage(st + STG);
    }

    // stage csum tile in smem (tiles region is dead now)
    float* csm = reinterpret_cast<float*>(smem + 1024);
    __syncthreads();
    csm[tid] = csum_g[n0 + tid];              // 256 threads cover BN=256
    __syncthreads();

    // ---------------- fused epilogue ----------------
    const int g  = lane >> 2;
    const int i2 = (lane & 3) * 2;
    const int col_off = (PHASE == 1) ? SO : 0;
    const bool tile_has_ux = (PHASE == 1) && (n0 < H1);

#pragma unroll
    for (int mi = 0; mi < 4; mi++) {
#pragma unroll
        for (int rr = 0; rr < 2; rr++) {
            const int row = m0 + wm * 64 + mi * 16 + g + rr * 8;
#pragma unroll
            for (int ni = 0; ni < 8; ni++) {
                const int lc  = wn * 64 + ni * 8 + i2;     // local col pair
                const int col = n0 + lc;
                float c0 = acc[mi][ni][rr * 2 + 0] + csm[lc + 0];
                float c1 = acc[mi][ni][rr * 2 + 1] + csm[lc + 1];
                if (tile_has_ux) {
                    float2 u = *reinterpret_cast<const float2*>(Ux + (size_t)row * H1 + col);
                    c0 += u.x; c1 += u.y;
                }
                float2 sv = *reinterpret_cast<const float2*>(
                    s_in + (size_t)row * (SE + SO) + col_off + col);
                const float h0 = 0.5f * c0, h1 = 0.5f * c1;
                // iters 0..7: tanh.approx (exact identity rhod = 1 - tanh^2(2s-1))
#pragma unroll
                for (int it = 0; it < NSTEP - 2; it++) {
                    float t0 = tanh_ap(fmaf(2.0f, sv.x, -1.0f));
                    float t1 = tanh_ap(fmaf(2.0f, sv.y, -1.0f));
                    sv.x = fmaf(-h0 * t0, t0, fmaf(0.5f, sv.x, h0));
                    sv.y = fmaf(-h1 * t1, t1, fmaf(0.5f, sv.y, h1));
                }
                // last 2 iters: exact sigmoid path (approx error from above decays)
                const float c20 = 2.0f * c0, c21 = 2.0f * c1;
#pragma unroll
                for (int it = 0; it < 2; it++) {
                    float q0  = ex2f(fmaf(RHO_A, sv.x, RHO_B));
                    float q1  = ex2f(fmaf(RHO_A, sv.y, RHO_B));
                    float rd0 = rcpf(1.0f + q0);
                    float rd1 = rcpf(1.0f + q1);
                    sv.x = fmaf(0.5f, sv.x, q0 * rd0 * rd0 * c20);
                    sv.y = fmaf(0.5f, sv.y, q1 * rd1 * rd1 * c21);
                }
                *reinterpret_cast<float2*>(out + (size_t)row * (SE + SO) + col_off + col) = sv;
                if (PHASE == 1) {
                    // rho(s)-0.5 = 0.5*tanh(2s-1); error ~ fp16 quantum, acceptable
                    float r0 = 0.5f * tanh_ap(fmaf(2.0f, sv.x, -1.0f));
                    float r1 = 0.5f * tanh_ap(fmaf(2.0f, sv.y, -1.0f));
                    *reinterpret_cast<__half2*>(g_A2 + (size_t)row * SE + col) =
                        __floats2half2_rn(r0, r1);
                }
            }
        }
    }
}

// ---------------------------------------------------------------------------
// Host: tensor-map encoding via driver entry point (no -lcuda needed)
// ---------------------------------------------------------------------------
typedef CUresult (*encode_fn_t)(CUtensorMap*, CUtensorMapDataType, cuuint32_t, void*,
                                const cuuint64_t*, const cuuint64_t*, const cuuint32_t*,
                                const cuuint32_t*, CUtensorMapInterleave, CUtensorMapSwizzle,
                                CUtensorMapL2promotion, CUtensorMapFloatOOBfill);

static void encode_tm(encode_fn_t enc, CUtensorMap* tm, void* base,
                      unsigned long long rows, unsigned box_rows) {
    cuuint64_t gd[2] = {2048ull, rows};
    cuuint64_t gs[1] = {4096ull};          // row stride in bytes
    cuuint32_t box[2] = {64u, box_rows};   // K box (128 B) x rows
    cuuint32_t es[2] = {1u, 1u};
    enc(tm, CU_TENSOR_MAP_DATA_TYPE_FLOAT16, 2, base, gd, gs, box, es,
        CU_TENSOR_MAP_INTERLEAVE_NONE, CU_TENSOR_MAP_SWIZZLE_128B,
        CU_TENSOR_MAP_L2_PROMOTION_L2_128B, CU_TENSOR_MAP_FLOAT_OOB_FILL_NONE);
}

extern "C" void kernel_launch(void* const* d_in, const int* in_sizes, int n_in,
                              void* d_out, int out_size) {
    const float* Ux     = (const float*)d_in[0];
    const float* s      = (const float*)d_in[1];
    const float* W      = (const float*)d_in[2];
    const float* b_even = (const float*)d_in[3];
    const float* b_odd  = (const float*)d_in[4];
    float* out = (float*)d_out;

    encode_fn_t enc = nullptr;
    cudaDriverEntryPointQueryResult qr;
    cudaGetDriverEntryPoint("cuTensorMapEncodeTiled", (void**)&enc, cudaEnableDefault, &qr);

    void *pA1, *pA2, *pW1, *pW2;
    cudaGetSymbolAddress(&pA1, g_A1);
    cudaGetSymbolAddress(&pA2, g_A2);
    cudaGetSymbolAddress(&pW1, g_W1);
    cudaGetSymbolAddress(&pW2, g_W2);

    CUtensorMap tmA1, tmA2, tmW1, tmW2;
    encode_tm(enc, &tmA1, pA1, BSZ, 128);
    encode_tm(enc, &tmA2, pA2, BSZ, 128);
    encode_tm(enc, &tmW1, pW1, SO, 256);
    encode_tm(enc, &tmW2, pW2, SE, 256);

    cudaFuncSetAttribute(gemm_fused<1>, cudaFuncAttributeMaxDynamicSharedMemorySize, SMEM_ALLOC);
    cudaFuncSetAttribute(gemm_fused<2>, cudaFuncAttributeMaxDynamicSharedMemorySize, SMEM_ALLOC);

    prepA_kernel<<<(BSZ * (SE / 4)) / 256, 256>>>(s);
    prepW_kernel<<<dim3(SO / 32, SE / 32), dim3(32, 8)>>>(W);
    prepSums_kernel<<<2048 + SE / 256, 256>>>(W, b_even, b_odd);

    dim3 grid(SO / BN, BSZ / BM);   // (8, 128)
    gemm_fused<1><<<grid, 256, SMEM_ALLOC>>>(tmA1, tmW1, s, Ux, out);
    gemm_fused<2><<<grid, 256, SMEM_ALLOC>>>(tmA2, tmW2, s, Ux, out);
}

// round 8
// speedup vs baseline: 1.5152x; 1.5152x over previous
#include <cuda_runtime.h>
#include <cuda.h>
#include <cuda_fp16.h>
#include <cstdint>

// Problem constants
#define BSZ   16384
#define SE    2048
#define SO    2048
#define H1    1024
#define NSTEP 10

// GEMM tiling (R6 proven config: 2 CTAs/SM)
#define BM 128
#define BN 128
#define BK 64
#define STG 3
#define ATILE 16384                     // 128 rows x 128 B
#define STAGE_BYTES (2 * ATILE)         // A + B
#define SMEM_ALLOC (STG * STAGE_BYTES + 1024)   // 99328 B -> 2 CTAs/SM

// ---------------------------------------------------------------------------
// Scratch (device globals; no allocation allowed)
// ---------------------------------------------------------------------------
__device__ __align__(1024) __half g_A1[(size_t)BSZ * SE];   // rho(s_even)-0.5
__device__ __align__(1024) __half g_A2[(size_t)BSZ * SE];   // rho(s_odd)-0.5
__device__ __align__(1024) __half g_W1[(size_t)SO * SE];    // W1[n][k] = W[k][n]
__device__ __align__(1024) __half g_W2[(size_t)SE * SO];    // W2[n][k] = W[n][k]
__device__ float g_csum1[SO];
__device__ float g_csum2[SE];

// ---------------------------------------------------------------------------
// Helpers
// ---------------------------------------------------------------------------
__device__ __forceinline__ float ex2f(float x) {
    float y; asm("ex2.approx.f32 %0, %1;" : "=f"(y) : "f"(x)); return y;
}
__device__ __forceinline__ float rcpf(float x) {
    float y; asm("rcp.approx.f32 %0, %1;" : "=f"(y) : "f"(x)); return y;
}
__device__ __forceinline__ float tanh_ap(float x) {
    float y; asm("tanh.approx.f32 %0, %1;" : "=f"(y) : "f"(x)); return y;
}
#define RHO_A (-5.770780163555852f)
#define RHO_B ( 2.885390081777926f)
__device__ __forceinline__ float rho_f(float x) {
    float q = ex2f(fmaf(RHO_A, x, RHO_B));
    return rcpf(1.0f + q);
}
__device__ __forceinline__ uint32_t cvta_smem(const void* p) {
    uint32_t a;
    asm("{ .reg .u64 t; cvta.to.shared.u64 t, %1; cvt.u32.u64 %0, t; }" : "=r"(a) : "l"(p));
    return a;
}
__device__ __forceinline__ void mbar_init(uint32_t a, uint32_t cnt) {
    asm volatile("mbarrier.init.shared.b64 [%0], %1;" :: "r"(a), "r"(cnt) : "memory");
}
__device__ __forceinline__ void mbar_expect_tx(uint32_t a, uint32_t b) {
    asm volatile("mbarrier.arrive.expect_tx.shared.b64 _, [%0], %1;" :: "r"(a), "r"(b) : "memory");
}
__device__ __forceinline__ void mbar_wait(uint32_t a, uint32_t ph) {
    asm volatile(
        "{\n\t.reg .pred P;\n"
        "LW%=:\n\t"
        "mbarrier.try_wait.parity.acquire.cta.shared::cta.b64 P, [%0], %1, 0x989680;\n\t"
        "@P bra LD%=;\n\t"
        "bra LW%=;\n"
        "LD%=:\n\t}"
        :: "r"(a), "r"(ph) : "memory");
}
__device__ __forceinline__ void tma2d(uint32_t dst, const CUtensorMap* tm, int x, int y, uint32_t mbar) {
    asm volatile(
        "cp.async.bulk.tensor.2d.shared::cta.global.tile.mbarrier::complete_tx::bytes "
        "[%0], [%1, {%2, %3}], [%4];"
        :: "r"(dst), "l"(tm), "r"(x), "r"(y), "r"(mbar) : "memory");
}
__device__ __forceinline__ void mma16816(float d[4], const uint32_t a[4], uint32_t b0, uint32_t b1) {
    asm volatile(
        "mma.sync.aligned.m16n8k16.row.col.f32.f16.f16.f32 "
        "{%0,%1,%2,%3}, {%4,%5,%6,%7}, {%8,%9}, {%0,%1,%2,%3};\n"
        : "+f"(d[0]), "+f"(d[1]), "+f"(d[2]), "+f"(d[3])
        : "r"(a[0]), "r"(a[1]), "r"(a[2]), "r"(a[3]), "r"(b0), "r"(b1));
}
__device__ __forceinline__ void ldsm4(uint32_t f[4], uint32_t addr) {
    asm volatile("ldmatrix.sync.aligned.m8n8.x4.shared.b16 {%0,%1,%2,%3}, [%4];\n"
                 : "=r"(f[0]), "=r"(f[1]), "=r"(f[2]), "=r"(f[3]) : "r"(addr));
}

// ---------------------------------------------------------------------------
// Prep kernels
// ---------------------------------------------------------------------------
__global__ void prepA_kernel(const float* __restrict__ s) {
    int id = blockIdx.x * blockDim.x + threadIdx.x;
    int m  = id >> 9;
    int kc = id & 511;
    float4 x = reinterpret_cast<const float4*>(s + (size_t)m * (SE + SO))[kc];
    float r0 = rho_f(x.x) - 0.5f;
    float r1 = rho_f(x.y) - 0.5f;
    float r2 = rho_f(x.z) - 0.5f;
    float r3 = rho_f(x.w) - 0.5f;
    __half2* dst = reinterpret_cast<__half2*>(g_A1 + (size_t)m * SE);
    dst[kc * 2 + 0] = __floats2half2_rn(r0, r1);
    dst[kc * 2 + 1] = __floats2half2_rn(r2, r3);
}

__global__ void prepW_kernel(const float* __restrict__ W) {
    __shared__ float tile[32][33];
    int bx = blockIdx.x * 32;   // n
    int by = blockIdx.y * 32;   // k
    int tx = threadIdx.x, ty = threadIdx.y;   // 32 x 8
#pragma unroll
    for (int j = 0; j < 32; j += 8) {
        int r = by + ty + j, c = bx + tx;
        float w = W[(size_t)r * SO + c];
        g_W2[(size_t)r * SO + c] = __float2half(w);
        tile[ty + j][tx] = w;
    }
    __syncthreads();
#pragma unroll
    for (int j = 0; j < 32; j += 8) {
        float w = tile[tx][ty + j];
        g_W1[(size_t)(bx + ty + j) * SE + by + tx] = __float2half(w);
    }
}

__global__ void prepSums_kernel(const float* __restrict__ W,
                                const float* __restrict__ b_even,
                                const float* __restrict__ b_odd) {
    if (blockIdx.x < 2048) {
        __shared__ float red[256];
        int n = blockIdx.x;
        float p = 0.f;
        for (int k = threadIdx.x; k < SO; k += 256) p += W[(size_t)n * SO + k];
        red[threadIdx.x] = p;
        __syncthreads();
        for (int st = 128; st > 0; st >>= 1) {
            if (threadIdx.x < st) red[threadIdx.x] += red[threadIdx.x + st];
            __syncthreads();
        }
        if (threadIdx.x == 0) g_csum2[n] = 0.5f * red[0] + b_even[n];
    } else {
        int c = (blockIdx.x - 2048) * 256 + threadIdx.x;
        float sum = 0.f;
        for (int k = 0; k < SE; k++) sum += W[(size_t)k * SO + c];
        g_csum1[c] = 0.5f * sum + b_odd[c];
    }
}

// ---------------------------------------------------------------------------
// Fused GEMM (TMA + HMMA, reg-pipelined frags) + all-tanh fixed-point iter
// ---------------------------------------------------------------------------
template <int PHASE>
__global__ void __launch_bounds__(256, 2)
gemm_fused(const __grid_constant__ CUtensorMap tmA,
           const __grid_constant__ CUtensorMap tmB,
           const float* __restrict__ s_in, const float* __restrict__ Ux,
           float* __restrict__ out) {
    extern __shared__ char smem[];
    const uint32_t s0 = cvta_smem(smem);
    const float* csum_g = (PHASE == 1) ? g_csum1 : g_csum2;

    const int tid  = threadIdx.x;
    const int warp = tid >> 5, lane = tid & 31;
    const int wm = warp & 1, wn = warp >> 1;     // 2 warps along M, 4 along N
    const int m0 = blockIdx.y * BM;
    const int n0 = blockIdx.x * BN;

    // block-sparse K range
    int k_lo, k_hi;
    if (PHASE == 1) { k_lo = 0; k_hi = (n0 < H1) ? 1024 : 2048; }
    else            { k_lo = (n0 < H1) ? 0 : 1024; k_hi = 2048; }
    const int total = (k_hi - k_lo) >> 6;        // 16 or 32 k-tiles, >= STG

    const uint32_t fullb = s0;                   // STG x 8 B barriers
    const uint32_t tbase = s0 + 1024;

    if (tid == 0) {
#pragma unroll
        for (int i = 0; i < STG; i++) mbar_init(fullb + 8 * i, 1);
    }
    __syncthreads();

    auto issue_stage = [&](int st) {
        const int b = st % STG;
        const uint32_t mb = fullb + 8 * b;
        const int kt = k_lo + st * BK;
        const uint32_t d = tbase + b * STAGE_BYTES;
        mbar_expect_tx(mb, STAGE_BYTES);
        tma2d(d,         &tmA, kt, m0, mb);
        tma2d(d + ATILE, &tmB, kt, n0, mb);
    };

    if (tid == 0) {
#pragma unroll
        for (int st = 0; st < STG; st++) issue_stage(st);
    }

    // loop-invariant ldmatrix address components
    const uint32_t arow = wm * 64 + (lane & 15);
    const uint32_t abit = (lane >> 4);
    const uint32_t brow = wn * 32 + ((lane >> 4) << 3) + (lane & 7);
    const uint32_t bbit = ((lane >> 3) & 1);

    float acc[4][4][4];
#pragma unroll
    for (int a = 0; a < 4; a++)
#pragma unroll
        for (int b = 0; b < 4; b++)
#pragma unroll
            for (int c = 0; c < 4; c++) acc[a][b][c] = 0.f;

    for (int st = 0; st < total; st++) {
        const int buf = st % STG;
        mbar_wait(fullb + 8 * buf, (st / STG) & 1);

        const uint32_t bufA = tbase + buf * STAGE_BYTES;
        const uint32_t bufB = bufA + ATILE;

        uint32_t af[2][4][4];
        uint32_t bf[2][2][4];

        auto ldfrags = [&](int ks, int slot) {
#pragma unroll
            for (int mi = 0; mi < 4; mi++) {
                uint32_t row = arow + mi * 16;
                uint32_t chunk = (ks * 2 + abit) ^ (row & 7);
                ldsm4(af[slot][mi], bufA + row * 128 + (chunk << 4));
            }
#pragma unroll
            for (int nj = 0; nj < 2; nj++) {
                uint32_t row = brow + nj * 16;
                uint32_t chunk = (ks * 2 + bbit) ^ (row & 7);
                ldsm4(bf[slot][nj], bufB + row * 128 + (chunk << 4));
            }
        };

        ldfrags(0, 0);
#pragma unroll
        for (int ks = 0; ks < 4; ks++) {
            const int cur = ks & 1;
            if (ks < 3) ldfrags(ks + 1, cur ^ 1);
#pragma unroll
            for (int mi = 0; mi < 4; mi++)
#pragma unroll
                for (int ni = 0; ni < 4; ni++)
                    mma16816(acc[mi][ni], af[cur][mi],
                             bf[cur][ni >> 1][(ni & 1) * 2],
                             bf[cur][ni >> 1][(ni & 1) * 2 + 1]);
        }
        __syncthreads();                      // all warps done with this buffer
        if (st + STG < total && tid == 0) issue_stage(st + STG);
    }

    // stage csum tile in smem (tiles region is dead now)
    float* csm = reinterpret_cast<float*>(smem + 1024);
    __syncthreads();
    if (tid < BN) csm[tid] = csum_g[n0 + tid];
    __syncthreads();

    // ---------------- fused epilogue (all-tanh: rhod = 1 - tanh^2(2s-1)) ----
    const int g  = lane >> 2;
    const int i2 = (lane & 3) * 2;
    const int col_off = (PHASE == 1) ? SO : 0;
    const bool tile_has_ux = (PHASE == 1) && (n0 < H1);

#pragma unroll
    for (int mi = 0; mi < 4; mi++) {
#pragma unroll
        for (int rr = 0; rr < 2; rr++) {
            const int row = m0 + wm * 64 + mi * 16 + g + rr * 8;
#pragma unroll
            for (int ni = 0; ni < 4; ni++) {
                const int lc  = wn * 32 + ni * 8 + i2;     // local col pair
                const int col = n0 + lc;
                float c0 = acc[mi][ni][rr * 2 + 0] + csm[lc + 0];
                float c1 = acc[mi][ni][rr * 2 + 1] + csm[lc + 1];
                if (tile_has_ux) {
                    float2 u = *reinterpret_cast<const float2*>(Ux + (size_t)row * H1 + col);
                    c0 += u.x; c1 += u.y;
                }
                float2 sv = *reinterpret_cast<const float2*>(
                    s_in + (size_t)row * (SE + SO) + col_off + col);
                const float h0 = 0.5f * c0, h1 = 0.5f * c1;
#pragma unroll
                for (int it = 0; it < NSTEP; it++) {
                    float t0 = tanh_ap(fmaf(2.0f, sv.x, -1.0f));
                    float t1 = tanh_ap(fmaf(2.0f, sv.y, -1.0f));
                    sv.x = fmaf(-h0 * t0, t0, fmaf(0.5f, sv.x, h0));
                    sv.y = fmaf(-h1 * t1, t1, fmaf(0.5f, sv.y, h1));
                }
                *reinterpret_cast<float2*>(out + (size_t)row * (SE + SO) + col_off + col) = sv;
                if (PHASE == 1) {
                    // rho(s)-0.5 = 0.5*tanh(2s-1)
                    float r0 = 0.5f * tanh_ap(fmaf(2.0f, sv.x, -1.0f));
                    float r1 = 0.5f * tanh_ap(fmaf(2.0f, sv.y, -1.0f));
                    *reinterpret_cast<__half2*>(g_A2 + (size_t)row * SE + col) =
                        __floats2half2_rn(r0, r1);
                }
            }
        }
    }
}

// ---------------------------------------------------------------------------
// Host: tensor-map encoding via driver entry point (no -lcuda needed)
// ---------------------------------------------------------------------------
typedef CUresult (*encode_fn_t)(CUtensorMap*, CUtensorMapDataType, cuuint32_t, void*,
                                const cuuint64_t*, const cuuint64_t*, const cuuint32_t*,
                                const cuuint32_t*, CUtensorMapInterleave, CUtensorMapSwizzle,
                                CUtensorMapL2promotion, CUtensorMapFloatOOBfill);

static void encode_tm(encode_fn_t enc, CUtensorMap* tm, void* base,
                      unsigned long long rows) {
    cuuint64_t gd[2] = {2048ull, rows};
    cuuint64_t gs[1] = {4096ull};          // row stride in bytes
    cuuint32_t box[2] = {64u, 128u};       // K box (128 B) x 128 rows
    cuuint32_t es[2] = {1u, 1u};
    enc(tm, CU_TENSOR_MAP_DATA_TYPE_FLOAT16, 2, base, gd, gs, box, es,
        CU_TENSOR_MAP_INTERLEAVE_NONE, CU_TENSOR_MAP_SWIZZLE_128B,
        CU_TENSOR_MAP_L2_PROMOTION_L2_128B, CU_TENSOR_MAP_FLOAT_OOB_FILL_NONE);
}

extern "C" void kernel_launch(void* const* d_in, const int* in_sizes, int n_in,
                              void* d_out, int out_size) {
    const float* Ux     = (const float*)d_in[0];
    const float* s      = (const float*)d_in[1];
    const float* W      = (const float*)d_in[2];
    const float* b_even = (const float*)d_in[3];
    const float* b_odd  = (const float*)d_in[4];
    float* out = (float*)d_out;

    encode_fn_t enc = nullptr;
    cudaDriverEntryPointQueryResult qr;
    cudaGetDriverEntryPoint("cuTensorMapEncodeTiled", (void**)&enc, cudaEnableDefault, &qr);

    void *pA1, *pA2, *pW1, *pW2;
    cudaGetSymbolAddress(&pA1, g_A1);
    cudaGetSymbolAddress(&pA2, g_A2);
    cudaGetSymbolAddress(&pW1, g_W1);
    cudaGetSymbolAddress(&pW2, g_W2);

    CUtensorMap tmA1, tmA2, tmW1, tmW2;
    encode_tm(enc, &tmA1, pA1, BSZ);
    encode_tm(enc, &tmA2, pA2, BSZ);
    encode_tm(enc, &tmW1, pW1, SO);
    encode_tm(enc, &tmW2, pW2, SE);

    cudaFuncSetAttribute(gemm_fused<1>, cudaFuncAttributeMaxDynamicSharedMemorySize, SMEM_ALLOC);
    cudaFuncSetAttribute(gemm_fused<2>, cudaFuncAttributeMaxDynamicSharedMemorySize, SMEM_ALLOC);

    prepA_kernel<<<(BSZ * (SE / 4)) / 256, 256>>>(s);
    prepW_kernel<<<dim3(SO / 32, SE / 32), dim3(32, 8)>>>(W);
    prepSums_kernel<<<2048 + SE / 256, 256>>>(W, b_even, b_odd);

    dim3 grid(SO / BN, BSZ / BM);   // (16, 128)
    gemm_fused<1><<<grid, 256, SMEM_ALLOC>>>(tmA1, tmW1, s, Ux, out);
    gemm_fused<2><<<grid, 256, SMEM_ALLOC>>>(tmA2, tmW2, s, Ux, out);
}

// round 9
// speedup vs baseline: 1.5885x; 1.0484x over previous
#include <cuda_runtime.h>
#include <cuda.h>
#include <cuda_fp16.h>
#include <cstdint>

// Problem constants
#define BSZ   16384
#define SE    2048
#define SO    2048
#define H1    1024
#define NSTEP 10

// GEMM tiling (2 CTAs/SM)
#define BM 128
#define BN 128
#define BK 64
#define STG 3
#define ATILE 16384                     // 128 rows x 128 B
#define STAGE_BYTES (2 * ATILE)         // A + B
#define SMEM_ALLOC (STG * STAGE_BYTES + 1024)   // 99328 B -> 2 CTAs/SM

// ---------------------------------------------------------------------------
// Scratch (device globals; no allocation allowed)
// ---------------------------------------------------------------------------
__device__ __align__(1024) __half g_A1[(size_t)BSZ * SE];   // rho(s_even)-0.5
__device__ __align__(1024) __half g_A2[(size_t)BSZ * SE];   // rho(s_odd)-0.5
__device__ __align__(1024) __half g_W1[(size_t)SO * SE];    // W1[n][k] = W[k][n]
__device__ __align__(1024) __half g_W2[(size_t)SE * SO];    // W2[n][k] = W[n][k]
__device__ float g_csum1[SO];
__device__ float g_csum2[SE];

// ---------------------------------------------------------------------------
// Helpers
// ---------------------------------------------------------------------------
__device__ __forceinline__ float ex2f(float x) {
    float y; asm("ex2.approx.f32 %0, %1;" : "=f"(y) : "f"(x)); return y;
}
__device__ __forceinline__ float rcpf(float x) {
    float y; asm("rcp.approx.f32 %0, %1;" : "=f"(y) : "f"(x)); return y;
}
__device__ __forceinline__ float tanh_ap(float x) {
    float y; asm("tanh.approx.f32 %0, %1;" : "=f"(y) : "f"(x)); return y;
}
#define RHO_A (-5.770780163555852f)
#define RHO_B ( 2.885390081777926f)
__device__ __forceinline__ float rho_f(float x) {
    float q = ex2f(fmaf(RHO_A, x, RHO_B));
    return rcpf(1.0f + q);
}
__device__ __forceinline__ uint32_t cvta_smem(const void* p) {
    uint32_t a;
    asm("{ .reg .u64 t; cvta.to.shared.u64 t, %1; cvt.u32.u64 %0, t; }" : "=r"(a) : "l"(p));
    return a;
}
__device__ __forceinline__ void mbar_init(uint32_t a, uint32_t cnt) {
    asm volatile("mbarrier.init.shared.b64 [%0], %1;" :: "r"(a), "r"(cnt) : "memory");
}
__device__ __forceinline__ void mbar_expect_tx(uint32_t a, uint32_t b) {
    asm volatile("mbarrier.arrive.expect_tx.shared.b64 _, [%0], %1;" :: "r"(a), "r"(b) : "memory");
}
__device__ __forceinline__ void mbar_arrive(uint32_t a) {
    asm volatile("mbarrier.arrive.release.cta.shared::cta.b64 _, [%0];" :: "r"(a) : "memory");
}
__device__ __forceinline__ void mbar_wait(uint32_t a, uint32_t ph) {
    asm volatile(
        "{\n\t.reg .pred P;\n"
        "LW%=:\n\t"
        "mbarrier.try_wait.parity.acquire.cta.shared::cta.b64 P, [%0], %1, 0x989680;\n\t"
        "@P bra LD%=;\n\t"
        "bra LW%=;\n"
        "LD%=:\n\t}"
        :: "r"(a), "r"(ph) : "memory");
}
__device__ __forceinline__ void tma2d(uint32_t dst, const CUtensorMap* tm, int x, int y, uint32_t mbar) {
    asm volatile(
        "cp.async.bulk.tensor.2d.shared::cta.global.tile.mbarrier::complete_tx::bytes "
        "[%0], [%1, {%2, %3}], [%4];"
        :: "r"(dst), "l"(tm), "r"(x), "r"(y), "r"(mbar) : "memory");
}
__device__ __forceinline__ void mma16816(float d[4], const uint32_t a[4], uint32_t b0, uint32_t b1) {
    asm volatile(
        "mma.sync.aligned.m16n8k16.row.col.f32.f16.f16.f32 "
        "{%0,%1,%2,%3}, {%4,%5,%6,%7}, {%8,%9}, {%0,%1,%2,%3};\n"
        : "+f"(d[0]), "+f"(d[1]), "+f"(d[2]), "+f"(d[3])
        : "r"(a[0]), "r"(a[1]), "r"(a[2]), "r"(a[3]), "r"(b0), "r"(b1));
}
__device__ __forceinline__ void ldsm4(uint32_t f[4], uint32_t addr) {
    asm volatile("ldmatrix.sync.aligned.m8n8.x4.shared.b16 {%0,%1,%2,%3}, [%4];\n"
                 : "=r"(f[0]), "=r"(f[1]), "=r"(f[2]), "=r"(f[3]) : "r"(addr));
}

// ---------------------------------------------------------------------------
// Prep kernels
// ---------------------------------------------------------------------------
__global__ void prepA_kernel(const float* __restrict__ s) {
    int id = blockIdx.x * blockDim.x + threadIdx.x;
    int m  = id >> 9;
    int kc = id & 511;
    float4 x = reinterpret_cast<const float4*>(s + (size_t)m * (SE + SO))[kc];
    float r0 = rho_f(x.x) - 0.5f;
    float r1 = rho_f(x.y) - 0.5f;
    float r2 = rho_f(x.z) - 0.5f;
    float r3 = rho_f(x.w) - 0.5f;
    __half2* dst = reinterpret_cast<__half2*>(g_A1 + (size_t)m * SE);
    dst[kc * 2 + 0] = __floats2half2_rn(r0, r1);
    dst[kc * 2 + 1] = __floats2half2_rn(r2, r3);
}

__global__ void prepW_kernel(const float* __restrict__ W) {
    __shared__ float tile[32][33];
    int bx = blockIdx.x * 32;   // n
    int by = blockIdx.y * 32;   // k
    int tx = threadIdx.x, ty = threadIdx.y;   // 32 x 8
#pragma unroll
    for (int j = 0; j < 32; j += 8) {
        int r = by + ty + j, c = bx + tx;
        float w = W[(size_t)r * SO + c];
        g_W2[(size_t)r * SO + c] = __float2half(w);
        tile[ty + j][tx] = w;
    }
    __syncthreads();
#pragma unroll
    for (int j = 0; j < 32; j += 8) {
        float w = tile[tx][ty + j];
        g_W1[(size_t)(bx + ty + j) * SE + by + tx] = __float2half(w);
    }
}

__global__ void prepSums_kernel(const float* __restrict__ W,
                                const float* __restrict__ b_even,
                                const float* __restrict__ b_odd) {
    if (blockIdx.x < 2048) {
        __shared__ float red[256];
        int n = blockIdx.x;
        float p = 0.f;
        for (int k = threadIdx.x; k < SO; k += 256) p += W[(size_t)n * SO + k];
        red[threadIdx.x] = p;
        __syncthreads();
        for (int st = 128; st > 0; st >>= 1) {
            if (threadIdx.x < st) red[threadIdx.x] += red[threadIdx.x + st];
            __syncthreads();
        }
        if (threadIdx.x == 0) g_csum2[n] = 0.5f * red[0] + b_even[n];
    } else {
        int c = (blockIdx.x - 2048) * 256 + threadIdx.x;
        float sum = 0.f;
        for (int k = 0; k < SE; k++) sum += W[(size_t)k * SO + c];
        g_csum1[c] = 0.5f * sum + b_odd[c];
    }
}

// ---------------------------------------------------------------------------
// Fused GEMM (TMA + HMMA, async consumed-barrier pipeline) + all-tanh iter
// ---------------------------------------------------------------------------
template <int PHASE>
__global__ void __launch_bounds__(256, 2)
gemm_fused(const __grid_constant__ CUtensorMap tmA,
           const __grid_constant__ CUtensorMap tmB,
           const float* __restrict__ s_in, const float* __restrict__ Ux,
           float* __restrict__ out) {
    extern __shared__ char smem[];
    const uint32_t s0 = cvta_smem(smem);
    const float* csum_g = (PHASE == 1) ? g_csum1 : g_csum2;

    const int tid  = threadIdx.x;
    const int warp = tid >> 5, lane = tid & 31;
    const int wm = warp & 1, wn = warp >> 1;     // 2 warps along M, 4 along N
    const int m0 = blockIdx.y * BM;

    // heavy-K tiles first to shrink last-wave tail
    int xr;
    if (PHASE == 1) xr = (blockIdx.x < 8) ? (int)blockIdx.x + 8 : (int)blockIdx.x - 8;
    else            xr = blockIdx.x;             // phase 2: natural order is heavy-first
    const int n0 = xr * BN;

    // block-sparse K range
    int k_lo, k_hi;
    if (PHASE == 1) { k_lo = 0; k_hi = (n0 < H1) ? 1024 : 2048; }
    else            { k_lo = (n0 < H1) ? 0 : 1024; k_hi = 2048; }
    const int total = (k_hi - k_lo) >> 6;        // 16 or 32 k-tiles, >= STG

    const uint32_t fullb = s0;                   // STG x 8 B (TMA tx barriers)
    const uint32_t consb = s0 + 64;              // STG x 8 B (consumed, 8 warp arrivals)
    const uint32_t tbase = s0 + 1024;

    if (tid == 0) {
#pragma unroll
        for (int i = 0; i < STG; i++) {
            mbar_init(fullb + 8 * i, 1);
            mbar_init(consb + 8 * i, 8);
        }
    }
    __syncthreads();

    auto issue_stage = [&](int st) {
        const int b = st % STG;
        const uint32_t mb = fullb + 8 * b;
        const int kt = k_lo + st * BK;
        const uint32_t d = tbase + b * STAGE_BYTES;
        mbar_expect_tx(mb, STAGE_BYTES);
        tma2d(d,         &tmA, kt, m0, mb);
        tma2d(d + ATILE, &tmB, kt, n0, mb);
    };

    if (tid == 0) {
#pragma unroll
        for (int st = 0; st < STG; st++) issue_stage(st);
    }

    // loop-invariant ldmatrix address components
    const uint32_t arow = wm * 64 + (lane & 15);
    const uint32_t abit = (lane >> 4);
    const uint32_t brow = wn * 32 + ((lane >> 4) << 3) + (lane & 7);
    const uint32_t bbit = ((lane >> 3) & 1);

    float acc[4][4][4];
#pragma unroll
    for (int a = 0; a < 4; a++)
#pragma unroll
        for (int b = 0; b < 4; b++)
#pragma unroll
            for (int c = 0; c < 4; c++) acc[a][b][c] = 0.f;

    for (int st = 0; st < total; st++) {
        const int buf = st % STG;
        const uint32_t ph = (st / STG) & 1;
        mbar_wait(fullb + 8 * buf, ph);

        const uint32_t bufA = tbase + buf * STAGE_BYTES;
        const uint32_t bufB = bufA + ATILE;

        uint32_t af[2][4][4];
        uint32_t bf[2][2][4];

        auto ldfrags = [&](int ks, int slot) {
#pragma unroll
            for (int mi = 0; mi < 4; mi++) {
                uint32_t row = arow + mi * 16;
                uint32_t chunk = (ks * 2 + abit) ^ (row & 7);
                ldsm4(af[slot][mi], bufA + row * 128 + (chunk << 4));
            }
#pragma unroll
            for (int nj = 0; nj < 2; nj++) {
                uint32_t row = brow + nj * 16;
                uint32_t chunk = (ks * 2 + bbit) ^ (row & 7);
                ldsm4(bf[slot][nj], bufB + row * 128 + (chunk << 4));
            }
        };

        ldfrags(0, 0);
#pragma unroll
        for (int ks = 0; ks < 4; ks++) {
            const int cur = ks & 1;
            if (ks < 3) ldfrags(ks + 1, cur ^ 1);
#pragma unroll
            for (int mi = 0; mi < 4; mi++)
#pragma unroll
                for (int ni = 0; ni < 4; ni++)
                    mma16816(acc[mi][ni], af[cur][mi],
                             bf[cur][ni >> 1][(ni & 1) * 2],
                             bf[cur][ni >> 1][(ni & 1) * 2 + 1]);
        }

        // this warp is done reading buffer `buf` (release orders the LDSM reads)
        if (lane == 0) mbar_arrive(consb + 8 * buf);
        // producer: refill once ALL warps have consumed this buffer
        if (tid == 0 && st + STG < total) {
            mbar_wait(consb + 8 * buf, ph);
            issue_stage(st + STG);
        }
    }

    // stage csum tile in smem (tiles region is dead now)
    float* csm = reinterpret_cast<float*>(smem + 1024);
    __syncthreads();
    if (tid < BN) csm[tid] = csum_g[n0 + tid];
    __syncthreads();

    // ---------------- fused epilogue (all-tanh: rhod = 1 - tanh^2(2s-1)) ----
    const int g  = lane >> 2;
    const int i2 = (lane & 3) * 2;
    const int col_off = (PHASE == 1) ? SO : 0;
    const bool tile_has_ux = (PHASE == 1) && (n0 < H1);

#pragma unroll
    for (int mi = 0; mi < 4; mi++) {
#pragma unroll
        for (int rr = 0; rr < 2; rr++) {
            const int row = m0 + wm * 64 + mi * 16 + g + rr * 8;
#pragma unroll
            for (int ni = 0; ni < 4; ni++) {
                const int lc  = wn * 32 + ni * 8 + i2;     // local col pair
                const int col = n0 + lc;
                float c0 = acc[mi][ni][rr * 2 + 0] + csm[lc + 0];
                float c1 = acc[mi][ni][rr * 2 + 1] + csm[lc + 1];
                if (tile_has_ux) {
                    float2 u = *reinterpret_cast<const float2*>(Ux + (size_t)row * H1 + col);
                    c0 += u.x; c1 += u.y;
                }
                float2 sv = *reinterpret_cast<const float2*>(
                    s_in + (size_t)row * (SE + SO) + col_off + col);
                const float h0 = 0.5f * c0, h1 = 0.5f * c1;
#pragma unroll
                for (int it = 0; it < NSTEP; it++) {
                    float t0 = tanh_ap(fmaf(2.0f, sv.x, -1.0f));
                    float t1 = tanh_ap(fmaf(2.0f, sv.y, -1.0f));
                    sv.x = fmaf(-h0 * t0, t0, fmaf(0.5f, sv.x, h0));
                    sv.y = fmaf(-h1 * t1, t1, fmaf(0.5f, sv.y, h1));
                }
                *reinterpret_cast<float2*>(out + (size_t)row * (SE + SO) + col_off + col) = sv;
                if (PHASE == 1) {
                    // rho(s)-0.5 = 0.5*tanh(2s-1)
                    float r0 = 0.5f * tanh_ap(fmaf(2.0f, sv.x, -1.0f));
                    float r1 = 0.5f * tanh_ap(fmaf(2.0f, sv.y, -1.0f));
                    *reinterpret_cast<__half2*>(g_A2 + (size_t)row * SE + col) =
                        __floats2half2_rn(r0, r1);
                }
            }
        }
    }
}

// ---------------------------------------------------------------------------
// Host: tensor-map encoding via driver entry point (no -lcuda needed)
// ---------------------------------------------------------------------------
typedef CUresult (*encode_fn_t)(CUtensorMap*, CUtensorMapDataType, cuuint32_t, void*,
                                const cuuint64_t*, const cuuint64_t*, const cuuint32_t*,
                                const cuuint32_t*, CUtensorMapInterleave, CUtensorMapSwizzle,
                                CUtensorMapL2promotion, CUtensorMapFloatOOBfill);

static void encode_tm(encode_fn_t enc, CUtensorMap* tm, void* base,
                      unsigned long long rows) {
    cuuint64_t gd[2] = {2048ull, rows};
    cuuint64_t gs[1] = {4096ull};          // row stride in bytes
    cuuint32_t box[2] = {64u, 128u};       // K box (128 B) x 128 rows
    cuuint32_t es[2] = {1u, 1u};
    enc(tm, CU_TENSOR_MAP_DATA_TYPE_FLOAT16, 2, base, gd, gs, box, es,
        CU_TENSOR_MAP_INTERLEAVE_NONE, CU_TENSOR_MAP_SWIZZLE_128B,
        CU_TENSOR_MAP_L2_PROMOTION_L2_128B, CU_TENSOR_MAP_FLOAT_OOB_FILL_NONE);
}

extern "C" void kernel_launch(void* const* d_in, const int* in_sizes, int n_in,
                              void* d_out, int out_size) {
    const float* Ux     = (const float*)d_in[0];
    const float* s      = (const float*)d_in[1];
    const float* W      = (const float*)d_in[2];
    const float* b_even = (const float*)d_in[3];
    const float* b_odd  = (const float*)d_in[4];
    float* out = (float*)d_out;

    encode_fn_t enc = nullptr;
    cudaDriverEntryPointQueryResult qr;
    cudaGetDriverEntryPoint("cuTensorMapEncodeTiled", (void**)&enc, cudaEnableDefault, &qr);

    void *pA1, *pA2, *pW1, *pW2;
    cudaGetSymbolAddress(&pA1, g_A1);
    cudaGetSymbolAddress(&pA2, g_A2);
    cudaGetSymbolAddress(&pW1, g_W1);
    cudaGetSymbolAddress(&pW2, g_W2);

    CUtensorMap tmA1, tmA2, tmW1, tmW2;
    encode_tm(enc, &tmA1, pA1, BSZ);
    encode_tm(enc, &tmA2, pA2, BSZ);
    encode_tm(enc, &tmW1, pW1, SO);
    encode_tm(enc, &tmW2, pW2, SE);

    cudaFuncSetAttribute(gemm_fused<1>, cudaFuncAttributeMaxDynamicSharedMemorySize, SMEM_ALLOC);
    cudaFuncSetAttribute(gemm_fused<2>, cudaFuncAttributeMaxDynamicSharedMemorySize, SMEM_ALLOC);

    prepA_kernel<<<(BSZ * (SE / 4)) / 256, 256>>>(s);
    prepW_kernel<<<dim3(SO / 32, SE / 32), dim3(32, 8)>>>(W);
    prepSums_kernel<<<2048 + SE / 256, 256>>>(W, b_even, b_odd);

    dim3 grid(SO / BN, BSZ / BM);   // (16, 128)
    gemm_fused<1><<<grid, 256, SMEM_ALLOC>>>(tmA1, tmW1, s, Ux, out);
    gemm_fused<2><<<grid, 256, SMEM_ALLOC>>>(tmA2, tmW2, s, Ux, out);
}